// round 14
// baseline (speedup 1.0000x reference)
#include <cuda_runtime.h>
#include <cuda_fp16.h>
#include <math.h>
#include <stdint.h>

#define NB     256
#define NA     128
#define NATOMS 32768
#define AEV    1008
#define AEVP   1024
#define MO     256
#define NOUT   128
#define FIN    384
#define NP     262144
#define NSP    4
#define NPAD   33280
#define NT     (NPAD/128)

// ---------------- scratch (device globals) ----------------------------------
__device__ __align__(16) __half g_f1h[(size_t)NPAD*FIN];
__device__ __align__(16) __half g_f2h[(size_t)NPAD*MO];
__device__ float g_feat2[(size_t)NPAD*FIN];     // fp32: internal1 | merged1
__device__ float g_neigh[(size_t)NPAD*NOUT];
__device__ float g_decay[NP];
__device__ int   g_e0[NP], g_e1[NP];
__device__ int   g_p2n[NATOMS];
__device__ int   g_n2o[NPAD];
__device__ int   g_tilesp[NT];
__device__ float g_pre[NATOMS];
// CSR adjacency (rebuilt every launch)
__device__ int   g_deg[NPAD];
__device__ int   g_roff[NPAD+1];
__device__ int   g_cur[NPAD];
__device__ int   g_nbr[2*NP];
__device__ float g_w[2*NP];
// transposed fp16 weights: [S][Nout][Kpad]
__device__ __align__(16) __half g_wm0h[(size_t)NSP*MO*AEVP];
__device__ __align__(16) __half g_wn0h[(size_t)NSP*NOUT*MO];
__device__ __align__(16) __half g_wm1h[(size_t)NSP*MO*FIN];
__device__ __align__(16) __half g_wn1h[(size_t)NSP*NOUT*MO];

// ---------------- small helpers ---------------------------------------------
__device__ __forceinline__ uint32_t smem_u32(const void* p){
    uint32_t a;
    asm("{ .reg .u64 t; cvta.to.shared.u64 t, %1; cvt.u32.u64 %0, t; }" : "=r"(a) : "l"(p));
    return a;
}
__device__ __forceinline__ void cp16(uint32_t dst, const void* src){
    asm volatile("cp.async.cg.shared.global [%0], [%1], 16;" :: "r"(dst), "l"(src) : "memory");
}
__device__ __forceinline__ void cp_commit(){
    asm volatile("cp.async.commit_group;" ::: "memory");
}
template<int N> __device__ __forceinline__ void cp_wait(){
    asm volatile("cp.async.wait_group %0;" :: "n"(N) : "memory");
}
__device__ __forceinline__ void ldsm4(uint32_t* r, uint32_t addr){
    asm volatile("ldmatrix.sync.aligned.m8n8.x4.shared.b16 {%0,%1,%2,%3}, [%4];"
        : "=r"(r[0]),"=r"(r[1]),"=r"(r[2]),"=r"(r[3]) : "r"(addr));
}
__device__ __forceinline__ void mma16816(float* d, const uint32_t* a, uint32_t b0, uint32_t b1){
    asm volatile("mma.sync.aligned.m16n8k16.row.col.f32.f16.f16.f32 "
        "{%0,%1,%2,%3}, {%4,%5,%6,%7}, {%8,%9}, {%0,%1,%2,%3};"
        : "+f"(d[0]),"+f"(d[1]),"+f"(d[2]),"+f"(d[3])
        : "r"(a[0]),"r"(a[1]),"r"(a[2]),"r"(a[3]), "r"(b0),"r"(b1));
}
__device__ __forceinline__ float gelu_tanh(float x){
    float t = tanhf(0.7978845608028654f * (x + 0.044715f * x * x * x));
    return 0.5f * x * (1.0f + t);
}

// ---------------- permutation: deterministic species grouping ---------------
__global__ void __launch_bounds__(1024) perm_kernel(const int* __restrict__ species){
    __shared__ int sc[NSP][1024];
    __shared__ int stot[NSP];
    __shared__ int sbase[NSP+1];
    int t = threadIdx.x;
    for (int r = t; r < NPAD; r += 1024){ g_n2o[r] = -1; g_deg[r] = 0; }
    int c0=0,c1=0,c2=0,c3=0;
    int b0 = t*32;
    #pragma unroll
    for (int j=0;j<32;j++){
        int s = species[b0+j];
        c0 += (s==0); c1 += (s==1); c2 += (s==2); c3 += (s==3);
    }
    sc[0][t]=c0; sc[1][t]=c1; sc[2][t]=c2; sc[3][t]=c3;
    __syncthreads();
    if (t < NSP){
        int run = 0;
        for (int i=0;i<1024;i++){ int v=sc[t][i]; sc[t][i]=run; run+=v; }
        stot[t]=run;
    }
    __syncthreads();
    if (t==0){
        int b=0;
        for (int s=0;s<NSP;s++){ sbase[s]=b; b += ((stot[s]+127)>>7)<<7; }
        sbase[NSP]=b;
        for (int tt=0; tt<NT; tt++){
            int rs = tt*128; int sp=0;
            for (int s=1;s<NSP;s++) if (rs >= sbase[s]) sp=s;
            g_tilesp[tt]=sp;
        }
    }
    __syncthreads();
    int run2[NSP] = {0,0,0,0};
    for (int j=0;j<32;j++){
        int i = b0+j; int s = species[i];
        int pos = sbase[s] + sc[s][t] + run2[s];
        run2[s]++;
        g_p2n[i]=pos; g_n2o[pos]=i;
    }
}

// ---------------- weight transpose: W[S][K][N] -> fp16 T[S][N][Kpad] --------
__global__ void __launch_bounds__(256) wprep_kernel(const float* __restrict__ W,
                                                    __half* __restrict__ Th,
                                                    int K, int Nout, int Kpad){
    long idx = (long)blockIdx.x*256 + threadIdx.x;
    long total = (long)NSP*Nout*Kpad;
    if (idx >= total) return;
    int k = idx % Kpad;
    int n = (idx / Kpad) % Nout;
    int s = idx / ((long)Kpad*Nout);
    float v = (k < K) ? W[((size_t)s*K + k)*Nout + n] : 0.f;
    Th[idx] = __float2half_rn(v);
}

// ---------------- edges: decay + endpoint remap + degree count ---------------
__global__ void edge_kernel(const int* __restrict__ ai,
                            const float* __restrict__ dist,
                            const float* __restrict__ fa,
                            const float* __restrict__ pf){
    int p = blockIdx.x*256 + threadIdx.x;
    float d = dist[p];
    float factor = fa[0], pre = pf[0];
    float x = fminf(fmaxf(d*(1.0f/5.2f), 0.0f), 1.0f - 1e-6f);
    float f = (d < 5.2f) ? expf(1.0f - 1.0f/(1.0f - x*x)) : 0.0f;
    g_decay[p] = pre*pre*expf(-factor*factor*d)*f;
    int e0 = g_p2n[ai[p]];
    int e1 = g_p2n[ai[NP + p]];
    g_e0[p] = e0; g_e1[p] = e1;
    atomicAdd(&g_deg[e0], 1);
    atomicAdd(&g_deg[e1], 1);
}

// ---------------- exclusive scan of degrees -> row offsets ------------------
#define SCAN_CH 33
__global__ void __launch_bounds__(1024) scan_kernel(){
    __shared__ int wsum[32];
    int t = threadIdx.x;
    int base = t*SCAN_CH;
    int s = 0;
    for (int j=0;j<SCAN_CH;j++){
        int idx = base+j;
        if (idx < NPAD) s += g_deg[idx];
    }
    int lane = t&31, w = t>>5;
    int v = s;
    #pragma unroll
    for (int o=1;o<32;o<<=1){ int u = __shfl_up_sync(~0u, v, o); if (lane>=o) v += u; }
    if (lane==31) wsum[w] = v;
    __syncthreads();
    if (w==0){
        int x = wsum[lane];
        #pragma unroll
        for (int o=1;o<32;o<<=1){ int u = __shfl_up_sync(~0u, x, o); if (lane>=o) x += u; }
        wsum[lane] = x;
    }
    __syncthreads();
    int excl = v - s + (w>0 ? wsum[w-1] : 0);
    int run = excl;
    for (int j=0;j<SCAN_CH;j++){
        int idx = base+j;
        if (idx < NPAD){
            g_roff[idx] = run;
            g_cur[idx]  = run;
            run += g_deg[idx];
        }
    }
    if (t == 1023) g_roff[NPAD] = run;
}

// ---------------- fill CSR edge lists -----------------------------------------
__global__ void fill_kernel(){
    int p = blockIdx.x*256 + threadIdx.x;
    int e0 = g_e0[p], e1 = g_e1[p];
    float d = g_decay[p];
    int i0 = atomicAdd(&g_cur[e0], 1);
    g_nbr[i0] = e1; g_w[i0] = d;
    int i1 = atomicAdd(&g_cur[e1], 1);
    g_nbr[i1] = e0; g_w[i1] = d;
}

#define PITCH 80
#define ATS   (128*PITCH)      // 10240 B: one 128-row tile (32 fp16/row)
#define STG   (2*ATS)          // ah | wh = 20480

// ===== unified tgemm: 256 thr, 2 CTA/SM, 2-stage, pure fp16, N=128/CTA ======
// grid = (Nout/128, NT). Optional fp32 A path (pass 0, indirected via g_n2o).
__global__ void __launch_bounds__(256, 2) tgemm_kernel(
    const float* __restrict__ A32,
    const __half* __restrict__ Ah, int lda,
    const __half* __restrict__ Wh, int WNout,
    const float* __restrict__ bias,
    int K,
    float* C32, int ldc32,
    __half* Ch, int ldcb,
    int act)
{
    extern __shared__ __align__(128) uint8_t sm[];   // 2*STG dynamic
    uint32_t smBase = smem_u32(sm);

    int tid = threadIdx.x, lane = tid & 31, wid = tid >> 5;
    int wm = wid & 3, wn = wid >> 2;
    int bx = blockIdx.x, by = blockIdx.y;
    int sp = g_tilesp[by];

    const __half* WhS = Wh + ((size_t)sp*WNout + bx*128)*K;

    float d[2][8][4];
    #pragma unroll
    for (int i=0;i<2;i++)
        #pragma unroll
        for (int j=0;j<8;j++)
            #pragma unroll
            for (int q=0;q<4;q++) d[i][j][q]=0.f;

    int nkc = K >> 5;

    uint32_t aoff = (uint32_t)((wm*32 + (lane & 15))*PITCH + ((lane >> 4) & 1)*16);
    uint32_t boff = (uint32_t)((wn*64 + (lane & 7) + ((lane >> 4) & 1)*8)*PITCH + ((lane >> 3) & 1)*16);

    auto do_mma = [&](int buf){
        uint32_t base = smBase + (uint32_t)buf*STG;
        #pragma unroll
        for (int ks=0; ks<2; ks++){
            uint32_t a_[2][4], b_[4][4];
            uint32_t aT = base + aoff + ks*32;
            uint32_t bT = base + ATS + boff + ks*32;
            #pragma unroll
            for (int mi=0; mi<2; mi++) ldsm4(a_[mi], aT + mi*16*PITCH);
            #pragma unroll
            for (int np_=0; np_<4; np_++) ldsm4(b_[np_], bT + np_*16*PITCH);
            #pragma unroll
            for (int mi=0; mi<2; mi++)
                #pragma unroll
                for (int nj=0; nj<8; nj++)
                    mma16816(d[mi][nj], a_[mi], b_[nj>>1][(nj&1)*2], b_[nj>>1][(nj&1)*2+1]);
        }
    };

    if (A32 == nullptr){
        // ---- fp16 A path: 4 cp16/thread (ah 512 | wh 512) ----
        const __half* AhR = Ah + (size_t)by*128*lda;
        auto load_chunk = [&](int kc, int buf){
            uint32_t base = smBase + (uint32_t)buf*STG;
            #pragma unroll
            for (int t=0;t<4;t++){
                int it = tid + t*256;     // 1024 items
                int tile = it >> 9;
                int j = it & 511;
                int row = j >> 2, seg = j & 3;
                const __half* src = (tile ? WhS + (size_t)row*K : AhR + (size_t)row*lda)
                                    + kc*32 + seg*8;
                cp16(base + (uint32_t)tile*ATS + row*PITCH + seg*16, src);
            }
            cp_commit();
        };
        load_chunk(0, 0);
        for (int c=0; c<nkc; c++){
            int buf = c & 1;
            if (c+1 < nkc){ load_chunk(c+1, buf^1); cp_wait<1>(); }
            else cp_wait<0>();
            __syncthreads();
            do_mma(buf);
            __syncthreads();
        }
    } else {
        // ---- fp32 A path (pass-0): LDG.128 + fp16 convert, 2-stage ----
        const float* aptr[4];
        bool avalid[4];
        int aRow[4], aSeg[4];
        #pragma unroll
        for (int t=0;t<4;t++){
            int j = tid + t*256;          // 1024 items: 128 rows x 8 segs(4 floats)
            aRow[t] = j >> 3; aSeg[t] = j & 7;
            int src = g_n2o[by*128 + aRow[t]];
            avalid[t] = (src >= 0);
            aptr[t] = A32 + (size_t)(src < 0 ? 0 : src)*AEV;
        }
        auto loadW = [&](int kc, int buf){
            uint32_t base = smBase + (uint32_t)buf*STG + ATS;
            #pragma unroll
            for (int t=0;t<2;t++){
                int j = tid + t*256;      // 512 items: 128 rows x 4 segs(16B)
                int row = j >> 2, seg = j & 3;
                cp16(base + row*PITCH + seg*16, WhS + (size_t)row*K + kc*32 + seg*8);
            }
            cp_commit();
        };
        float4 R[4];
        auto ldgA = [&](int kc){
            #pragma unroll
            for (int t=0;t<4;t++){
                int col = kc*32 + aSeg[t]*4;
                if (avalid[t] && col < AEV) R[t] = *(const float4*)(aptr[t] + col);
                else R[t] = make_float4(0.f,0.f,0.f,0.f);
            }
        };
        auto stsA = [&](int buf){
            uint32_t base = (uint32_t)buf*STG;
            #pragma unroll
            for (int t=0;t<4;t++){
                __half h[4];
                h[0] = __float2half_rn(R[t].x);
                h[1] = __float2half_rn(R[t].y);
                h[2] = __float2half_rn(R[t].z);
                h[3] = __float2half_rn(R[t].w);
                uint32_t off = base + (uint32_t)(aRow[t]*PITCH + aSeg[t]*8);
                *(uint64_t*)(sm + off) = *(const uint64_t*)h;
            }
        };
        ldgA(0);
        loadW(0, 0);
        for (int c=0; c<nkc; c++){
            int buf = c & 1;
            stsA(buf);
            if (c+1 < nkc){ ldgA(c+1); loadW(c+1, buf^1); cp_wait<1>(); }
            else cp_wait<0>();
            __syncthreads();
            do_mma(buf);
            __syncthreads();
        }
    }

    const float* bp = bias + sp*WNout + bx*128 + wn*64;
    int rowLo = wm*32 + (lane >> 2);
    int colCta = bx*128 + wn*64;
    #pragma unroll
    for (int mi=0; mi<2; mi++){
        #pragma unroll
        for (int nj=0; nj<8; nj++){
            int c0 = nj*8 + 2*(lane & 3);
            float b0 = bp[c0], b1 = bp[c0+1];
            #pragma unroll
            for (int h=0; h<2; h++){
                size_t gr = (size_t)by*128 + rowLo + mi*16 + h*8;
                float x0 = d[mi][nj][2*h]   + b0;
                float x1 = d[mi][nj][2*h+1] + b1;
                if (act){ x0 = gelu_tanh(x0); x1 = gelu_tanh(x1); }
                int col = colCta + c0;
                if (C32)
                    *(float2*)(C32 + gr*ldc32 + col) = make_float2(x0, x1);
                if (Ch){
                    uint32_t hh = (uint32_t)__half_as_ushort(__float2half_rn(x0)) |
                                  ((uint32_t)__half_as_ushort(__float2half_rn(x1)) << 16);
                    *(uint32_t*)(Ch + gr*ldcb + col) = hh;
                }
            }
        }
    }
}

// ---------------- CSR gather: merged[r][t] = sum_nb neigh[nb][t]*w ----------
__global__ void __launch_bounds__(128) mpgather_kernel(int mode){
    int r = blockIdx.x, t = threadIdx.x;
    int s = g_roff[r], e = g_roff[r+1];
    float acc = 0.f;
    int j = s;
    for (; j+1 < e; j += 2){
        int nb0 = g_nbr[j], nb1 = g_nbr[j+1];
        float w0 = g_w[j],  w1 = g_w[j+1];
        float x0 = g_neigh[(size_t)nb0*NOUT + t];
        float x1 = g_neigh[(size_t)nb1*NOUT + t];
        acc = fmaf(x0, w0, acc);
        acc = fmaf(x1, w1, acc);
    }
    if (j < e)
        acc = fmaf(g_neigh[(size_t)g_nbr[j]*NOUT + t], g_w[j], acc);
    if (mode == 0){
        g_f1h[(size_t)r*FIN + 256 + t] = __float2half_rn(acc);
    } else {
        g_feat2[(size_t)r*FIN + 256 + t] = acc;
    }
}

// ---------------- final routed linear (FIN->1) + outputs --------------------
__global__ void __launch_bounds__(256) final_kernel(const int* __restrict__ species,
                                                    const float* __restrict__ Wf,
                                                    const float* __restrict__ bf,
                                                    float* __restrict__ out){
    int gt = blockIdx.x*256 + threadIdx.x;
    int i = gt >> 5, lane = gt & 31;
    if (i >= NATOMS) return;
    int s = species[i];
    int r = g_p2n[i];
    const float* f = g_feat2 + (size_t)r*FIN;
    const float* w = Wf + s*FIN;
    float sum = 0.f;
    #pragma unroll
    for (int j=0;j<12;j++){
        int k = lane + 32*j;
        sum = fmaf(f[k], w[k], sum);
    }
    #pragma unroll
    for (int o=16;o;o>>=1) sum += __shfl_xor_sync(0xffffffffu, sum, o);
    if (lane == 0){
        float pre = sum + bf[s];
        g_pre[i] = pre;
        out[2*NATOMS + i] = pre;
        out[i] = (float)s;
    }
}

// ---------------- per-molecule charge redistribution -------------------------
__global__ void charge_kernel(const float* __restrict__ tq, float* __restrict__ out){
    __shared__ float ss[4];
    int b = blockIdx.x, a = threadIdx.x;
    float p = g_pre[b*NA + a];
    float v = p;
    #pragma unroll
    for (int o=16;o;o>>=1) v += __shfl_xor_sync(0xffffffffu, v, o);
    int w = a>>5, lane = a&31;
    if (lane == 0) ss[w] = v;
    __syncthreads();
    float sum = ss[0]+ss[1]+ss[2]+ss[3];
    out[NATOMS + b*NA + a] = p + (tq[b] - sum)*(1.0f/128.0f);
}

// ---------------- launch -----------------------------------------------------
extern "C" void kernel_launch(void* const* d_in, const int* in_sizes, int n_in,
                              void* d_out, int out_size){
    const int*   species = (const int*)  d_in[0];
    const float* aev     = (const float*)d_in[1];
    const int*   ai12    = (const int*)  d_in[2];
    const float* dist    = (const float*)d_in[3];
    const float* tq      = (const float*)d_in[4];
    const float* Wm0     = (const float*)d_in[5];
    const float* bm0     = (const float*)d_in[6];
    const float* Wn0     = (const float*)d_in[7];
    const float* bn0     = (const float*)d_in[8];
    const float* Wm1     = (const float*)d_in[9];
    const float* bm1     = (const float*)d_in[10];
    const float* Wn1     = (const float*)d_in[11];
    const float* bn1     = (const float*)d_in[12];
    const float* Wf      = (const float*)d_in[13];
    const float* bf      = (const float*)d_in[14];
    const float* factor  = (const float*)d_in[15];
    const float* prefac  = (const float*)d_in[16];
    float* out = (float*)d_out;

    __half *f1h, *f2h, *wm0h, *wn0h, *wm1h, *wn1h;
    float *feat2, *neigh;
    cudaGetSymbolAddress((void**)&f1h,  g_f1h);
    cudaGetSymbolAddress((void**)&f2h,  g_f2h);
    cudaGetSymbolAddress((void**)&wm0h, g_wm0h);
    cudaGetSymbolAddress((void**)&wn0h, g_wn0h);
    cudaGetSymbolAddress((void**)&wm1h, g_wm1h);
    cudaGetSymbolAddress((void**)&wn1h, g_wn1h);
    cudaGetSymbolAddress((void**)&feat2, g_feat2);
    cudaGetSymbolAddress((void**)&neigh, g_neigh);

    cudaFuncSetAttribute(tgemm_kernel, cudaFuncAttributeMaxDynamicSharedMemorySize, 2*STG);

    static cudaStream_t s1 = 0, s2 = 0;
    static cudaEvent_t evStart=0, evPerm=0, evW0m=0, evWn0=0, evW1m=0, evWrest=0, evCsr=0;
    if (!s1){
        cudaStreamCreateWithFlags(&s1, cudaStreamNonBlocking);
        cudaStreamCreateWithFlags(&s2, cudaStreamNonBlocking);
        cudaEventCreateWithFlags(&evStart, cudaEventDisableTiming);
        cudaEventCreateWithFlags(&evPerm,  cudaEventDisableTiming);
        cudaEventCreateWithFlags(&evW0m,   cudaEventDisableTiming);
        cudaEventCreateWithFlags(&evWn0,   cudaEventDisableTiming);
        cudaEventCreateWithFlags(&evW1m,   cudaEventDisableTiming);
        cudaEventCreateWithFlags(&evWrest, cudaEventDisableTiming);
        cudaEventCreateWithFlags(&evCsr,   cudaEventDisableTiming);
    }

    // fork s2: weight prep in consumption order
    cudaEventRecord(evStart, 0);
    cudaStreamWaitEvent(s2, evStart, 0);
    wprep_kernel<<<(NSP*MO*AEVP)/256, 256, 0, s2>>>(Wm0, wm0h, AEV, MO, AEVP);
    cudaEventRecord(evW0m, s2);
    wprep_kernel<<<(NSP*NOUT*MO)/256, 256, 0, s2>>>(Wn0, wn0h, MO, NOUT, MO);
    cudaEventRecord(evWn0, s2);
    wprep_kernel<<<(NSP*MO*FIN)/256, 256, 0, s2>>>(Wm1, wm1h, FIN, MO, FIN);
    cudaEventRecord(evW1m, s2);
    wprep_kernel<<<(NSP*NOUT*MO)/256, 256, 0, s2>>>(Wn1, wn1h, MO, NOUT, MO);
    cudaEventRecord(evWrest, s2);

    // main: permutation; fork s1: CSR build
    perm_kernel<<<1, 1024>>>(species);
    cudaEventRecord(evPerm, 0);
    cudaStreamWaitEvent(s1, evPerm, 0);
    edge_kernel<<<NP/256, 256, 0, s1>>>(ai12, dist, factor, prefac);
    scan_kernel<<<1, 1024, 0, s1>>>();
    fill_kernel<<<NP/256, 256, 0, s1>>>();
    cudaEventRecord(evCsr, s1);

    // pass 0
    cudaStreamWaitEvent(0, evW0m, 0);
    tgemm_kernel<<<dim3(2, NT), 256, 2*STG>>>(aev,
        (__half*)0, 0, wm0h, MO, bm0, AEVP,
        (float*)0, 0, f1h, FIN, 1);
    cudaStreamWaitEvent(0, evWn0, 0);
    tgemm_kernel<<<dim3(1, NT), 256, 2*STG>>>((const float*)0,
        f1h, FIN, wn0h, NOUT, bn0, MO,
        neigh, NOUT, (__half*)0, 0, 1);
    cudaStreamWaitEvent(0, evCsr, 0);
    mpgather_kernel<<<NPAD, 128>>>(0);

    // pass 1
    cudaStreamWaitEvent(0, evW1m, 0);
    tgemm_kernel<<<dim3(2, NT), 256, 2*STG>>>((const float*)0,
        f1h, FIN, wm1h, MO, bm1, FIN,
        feat2, FIN, f2h, MO, 1);
    cudaStreamWaitEvent(0, evWrest, 0);
    tgemm_kernel<<<dim3(1, NT), 256, 2*STG>>>((const float*)0,
        f2h, MO, wn1h, NOUT, bn1, MO,
        neigh, NOUT, (__half*)0, 0, 1);
    mpgather_kernel<<<NPAD, 128>>>(1);

    // outputs
    final_kernel <<<NATOMS*32/256, 256>>>(species, Wf, bf, out);
    charge_kernel<<<NB, NA>>>(tq, out);
}

// round 15
// speedup vs baseline: 1.1132x; 1.1132x over previous
#include <cuda_runtime.h>
#include <cuda_fp16.h>
#include <math.h>
#include <stdint.h>

#define NB     256
#define NA     128
#define NATOMS 32768
#define AEV    1008
#define AEVP   1024
#define MO     256
#define NOUT   128
#define FIN    384
#define NP     262144
#define NSP    4
#define NPAD   33280
#define NT     (NPAD/128)

// ---------------- scratch (device globals) ----------------------------------
__device__ __align__(16) __half g_f1h[(size_t)NPAD*FIN];
__device__ __align__(16) __half g_f2h[(size_t)NPAD*MO];
__device__ float g_feat2[(size_t)NPAD*FIN];     // fp32: internal1 | merged1
__device__ float g_neigh[(size_t)NPAD*NOUT];
__device__ float g_decay[NP];
__device__ int   g_e0[NP], g_e1[NP];
__device__ int   g_p2n[NATOMS];
__device__ int   g_n2o[NPAD];
__device__ int   g_tilesp[NT];
__device__ float g_pre[NATOMS];
// CSR adjacency (rebuilt every launch)
__device__ int   g_deg[NPAD];
__device__ int   g_roff[NPAD+1];
__device__ int   g_cur[NPAD];
__device__ int   g_nbr[2*NP];
__device__ float g_w[2*NP];
// transposed fp16 weights: [S][Nout][Kpad]
__device__ __align__(16) __half g_wm0h[(size_t)NSP*MO*AEVP];
__device__ __align__(16) __half g_wn0h[(size_t)NSP*NOUT*MO];
__device__ __align__(16) __half g_wm1h[(size_t)NSP*MO*FIN];
__device__ __align__(16) __half g_wn1h[(size_t)NSP*NOUT*MO];

// ---------------- small helpers ---------------------------------------------
__device__ __forceinline__ uint32_t smem_u32(const void* p){
    uint32_t a;
    asm("{ .reg .u64 t; cvta.to.shared.u64 t, %1; cvt.u32.u64 %0, t; }" : "=r"(a) : "l"(p));
    return a;
}
__device__ __forceinline__ void cp16(uint32_t dst, const void* src){
    asm volatile("cp.async.cg.shared.global [%0], [%1], 16;" :: "r"(dst), "l"(src) : "memory");
}
__device__ __forceinline__ void cp_commit(){
    asm volatile("cp.async.commit_group;" ::: "memory");
}
template<int N> __device__ __forceinline__ void cp_wait(){
    asm volatile("cp.async.wait_group %0;" :: "n"(N) : "memory");
}
__device__ __forceinline__ void ldsm4(uint32_t* r, uint32_t addr){
    asm volatile("ldmatrix.sync.aligned.m8n8.x4.shared.b16 {%0,%1,%2,%3}, [%4];"
        : "=r"(r[0]),"=r"(r[1]),"=r"(r[2]),"=r"(r[3]) : "r"(addr));
}
__device__ __forceinline__ void mma16816(float* d, const uint32_t* a, uint32_t b0, uint32_t b1){
    asm volatile("mma.sync.aligned.m16n8k16.row.col.f32.f16.f16.f32 "
        "{%0,%1,%2,%3}, {%4,%5,%6,%7}, {%8,%9}, {%0,%1,%2,%3};"
        : "+f"(d[0]),"+f"(d[1]),"+f"(d[2]),"+f"(d[3])
        : "r"(a[0]),"r"(a[1]),"r"(a[2]),"r"(a[3]), "r"(b0),"r"(b1));
}
__device__ __forceinline__ float gelu_tanh(float x){
    float t = tanhf(0.7978845608028654f * (x + 0.044715f * x * x * x));
    return 0.5f * x * (1.0f + t);
}

// ---------------- permutation: deterministic species grouping ---------------
__global__ void __launch_bounds__(1024) perm_kernel(const int* __restrict__ species){
    __shared__ int sc[NSP][1024];
    __shared__ int stot[NSP];
    __shared__ int sbase[NSP+1];
    int t = threadIdx.x;
    for (int r = t; r < NPAD; r += 1024){ g_n2o[r] = -1; g_deg[r] = 0; }
    int c0=0,c1=0,c2=0,c3=0;
    int b0 = t*32;
    #pragma unroll
    for (int j=0;j<32;j++){
        int s = species[b0+j];
        c0 += (s==0); c1 += (s==1); c2 += (s==2); c3 += (s==3);
    }
    sc[0][t]=c0; sc[1][t]=c1; sc[2][t]=c2; sc[3][t]=c3;
    __syncthreads();
    if (t < NSP){
        int run = 0;
        for (int i=0;i<1024;i++){ int v=sc[t][i]; sc[t][i]=run; run+=v; }
        stot[t]=run;
    }
    __syncthreads();
    if (t==0){
        int b=0;
        for (int s=0;s<NSP;s++){ sbase[s]=b; b += ((stot[s]+127)>>7)<<7; }
        sbase[NSP]=b;
        for (int tt=0; tt<NT; tt++){
            int rs = tt*128; int sp=0;
            for (int s=1;s<NSP;s++) if (rs >= sbase[s]) sp=s;
            g_tilesp[tt]=sp;
        }
    }
    __syncthreads();
    int run2[NSP] = {0,0,0,0};
    for (int j=0;j<32;j++){
        int i = b0+j; int s = species[i];
        int pos = sbase[s] + sc[s][t] + run2[s];
        run2[s]++;
        g_p2n[i]=pos; g_n2o[pos]=i;
    }
}

// ---------------- weight transpose: W[S][K][N] -> fp16 T[S][N][Kpad] --------
__global__ void __launch_bounds__(256) wprep_kernel(const float* __restrict__ W,
                                                    __half* __restrict__ Th,
                                                    int K, int Nout, int Kpad){
    long idx = (long)blockIdx.x*256 + threadIdx.x;
    long total = (long)NSP*Nout*Kpad;
    if (idx >= total) return;
    int k = idx % Kpad;
    int n = (idx / Kpad) % Nout;
    int s = idx / ((long)Kpad*Nout);
    float v = (k < K) ? W[((size_t)s*K + k)*Nout + n] : 0.f;
    Th[idx] = __float2half_rn(v);
}

// ---------------- edges: decay + endpoint remap + degree count ---------------
__global__ void edge_kernel(const int* __restrict__ ai,
                            const float* __restrict__ dist,
                            const float* __restrict__ fa,
                            const float* __restrict__ pf){
    int p = blockIdx.x*256 + threadIdx.x;
    float d = dist[p];
    float factor = fa[0], pre = pf[0];
    float x = fminf(fmaxf(d*(1.0f/5.2f), 0.0f), 1.0f - 1e-6f);
    float f = (d < 5.2f) ? expf(1.0f - 1.0f/(1.0f - x*x)) : 0.0f;
    g_decay[p] = pre*pre*expf(-factor*factor*d)*f;
    int e0 = g_p2n[ai[p]];
    int e1 = g_p2n[ai[NP + p]];
    g_e0[p] = e0; g_e1[p] = e1;
    atomicAdd(&g_deg[e0], 1);
    atomicAdd(&g_deg[e1], 1);
}

// ---------------- exclusive scan of degrees -> row offsets ------------------
#define SCAN_CH 33
__global__ void __launch_bounds__(1024) scan_kernel(){
    __shared__ int wsum[32];
    int t = threadIdx.x;
    int base = t*SCAN_CH;
    int s = 0;
    for (int j=0;j<SCAN_CH;j++){
        int idx = base+j;
        if (idx < NPAD) s += g_deg[idx];
    }
    int lane = t&31, w = t>>5;
    int v = s;
    #pragma unroll
    for (int o=1;o<32;o<<=1){ int u = __shfl_up_sync(~0u, v, o); if (lane>=o) v += u; }
    if (lane==31) wsum[w] = v;
    __syncthreads();
    if (w==0){
        int x = wsum[lane];
        #pragma unroll
        for (int o=1;o<32;o<<=1){ int u = __shfl_up_sync(~0u, x, o); if (lane>=o) x += u; }
        wsum[lane] = x;
    }
    __syncthreads();
    int excl = v - s + (w>0 ? wsum[w-1] : 0);
    int run = excl;
    for (int j=0;j<SCAN_CH;j++){
        int idx = base+j;
        if (idx < NPAD){
            g_roff[idx] = run;
            g_cur[idx]  = run;
            run += g_deg[idx];
        }
    }
    if (t == 1023) g_roff[NPAD] = run;
}

// ---------------- fill CSR edge lists -----------------------------------------
__global__ void fill_kernel(){
    int p = blockIdx.x*256 + threadIdx.x;
    int e0 = g_e0[p], e1 = g_e1[p];
    float d = g_decay[p];
    int i0 = atomicAdd(&g_cur[e0], 1);
    g_nbr[i0] = e1; g_w[i0] = d;
    int i1 = atomicAdd(&g_cur[e1], 1);
    g_nbr[i1] = e0; g_w[i1] = d;
}

// K-chunk = 64 fp16 = 128 B + 16 pad -> PITCH 144 (16B aligned, ldsm conflict-free)
#define PITCH 144
#define ATS   (128*PITCH)      // 18432 B: one 128-row tile (64 fp16/row)
#define WTS   (256*PITCH)      // 36864 B: one 256-row W tile

// ============ tgemm128: N=128 pure fp16, 2-stage, 2 CTA/SM ==================
#define STG128 (2*ATS)         // ah | wh = 36864
__global__ void __launch_bounds__(256, 2) tgemm128_kernel(
    const __half* __restrict__ Ah, int lda,
    const __half* __restrict__ Wh,
    const float* __restrict__ bias,
    int K, float* C32, int ldc32, int act)
{
    extern __shared__ __align__(128) uint8_t sm[];
    uint32_t smBase = smem_u32(sm);
    const int Nout = 128;

    int tid = threadIdx.x, lane = tid & 31, wid = tid >> 5;
    int wm = wid & 3, wn = wid >> 2;
    int by = blockIdx.x;
    int sp = g_tilesp[by];

    const __half* AhR = Ah + (size_t)by*128*lda;
    const __half* WhS = Wh + (size_t)sp*Nout*K;

    float d[2][8][4];
    #pragma unroll
    for (int i=0;i<2;i++)
        #pragma unroll
        for (int j=0;j<8;j++)
            #pragma unroll
            for (int q=0;q<4;q++) d[i][j][q]=0.f;

    int nkc = K >> 6;

    uint32_t aoff = (uint32_t)((wm*32 + (lane & 15))*PITCH + ((lane >> 4) & 1)*16);
    uint32_t boff = (uint32_t)((wn*64 + (lane & 7) + ((lane >> 4) & 1)*8)*PITCH + ((lane >> 3) & 1)*16);

    auto load_chunk = [&](int kc, int buf){
        uint32_t base = smBase + (uint32_t)buf*STG128;
        #pragma unroll
        for (int t=0;t<8;t++){
            int it = tid + t*256;     // 2048 items: ah 1024 | wh 1024
            int tile = it >> 10;
            int j = it & 1023;
            int row = j >> 3, seg = j & 7;
            const __half* src = (tile ? WhS + (size_t)row*K : AhR + (size_t)row*lda)
                                + kc*64 + seg*8;
            cp16(base + (uint32_t)tile*ATS + row*PITCH + seg*16, src);
        }
        cp_commit();
    };

    auto do_mma = [&](int buf){
        uint32_t base = smBase + (uint32_t)buf*STG128;
        #pragma unroll
        for (int ks=0; ks<4; ks++){
            uint32_t a_[2][4], b_[4][4];
            uint32_t aT = base + aoff + ks*32;
            uint32_t bT = base + ATS + boff + ks*32;
            #pragma unroll
            for (int mi=0; mi<2; mi++) ldsm4(a_[mi], aT + mi*16*PITCH);
            #pragma unroll
            for (int np_=0; np_<4; np_++) ldsm4(b_[np_], bT + np_*16*PITCH);
            #pragma unroll
            for (int mi=0; mi<2; mi++)
                #pragma unroll
                for (int nj=0; nj<8; nj++)
                    mma16816(d[mi][nj], a_[mi], b_[nj>>1][(nj&1)*2], b_[nj>>1][(nj&1)*2+1]);
        }
    };

    load_chunk(0, 0);
    for (int c=0; c<nkc; c++){
        int buf = c & 1;
        if (c+1 < nkc){ load_chunk(c+1, buf^1); cp_wait<1>(); }
        else cp_wait<0>();
        __syncthreads();
        do_mma(buf);
        __syncthreads();
    }

    const float* bp = bias + sp*Nout + wn*64;
    int rowLo = wm*32 + (lane >> 2);
    int colCta = wn*64;
    #pragma unroll
    for (int mi=0; mi<2; mi++){
        #pragma unroll
        for (int nj=0; nj<8; nj++){
            int c0 = nj*8 + 2*(lane & 3);
            float b0 = bp[c0], b1 = bp[c0+1];
            #pragma unroll
            for (int h=0; h<2; h++){
                size_t gr = (size_t)by*128 + rowLo + mi*16 + h*8;
                float x0 = d[mi][nj][2*h]   + b0;
                float x1 = d[mi][nj][2*h+1] + b1;
                if (act){ x0 = gelu_tanh(x0); x1 = gelu_tanh(x1); }
                *(float2*)(C32 + gr*ldc32 + colCta + c0) = make_float2(x0, x1);
            }
        }
    }
}

// ============ tgemm256: N=256 mega-CTA pure fp16, 3-stage ===================
#define STG3  (ATS + WTS)      // 55296: ah | wh
__global__ void __launch_bounds__(512, 1) tgemm256_kernel(
    const float* __restrict__ A32,
    const __half* __restrict__ Ah, int lda,
    const __half* __restrict__ Wh,
    const float* __restrict__ bias,
    int K,
    float* C32, int ldc32,
    __half* Ch, int ldcb)
{
    extern __shared__ __align__(128) uint8_t sm[];   // 3*STG3 dynamic
    uint32_t smBase = smem_u32(sm);
    const int Nout = 256;

    int tid = threadIdx.x, lane = tid & 31, wid = tid >> 5;
    int wm = wid & 3, wn = wid >> 2;     // 4 x 4 warp grid: 128 x 256
    int by = blockIdx.x;
    int sp = g_tilesp[by];

    const __half* WhS = Wh + (size_t)sp*Nout*K;

    float d[2][8][4];
    #pragma unroll
    for (int i=0;i<2;i++)
        #pragma unroll
        for (int j=0;j<8;j++)
            #pragma unroll
            for (int q=0;q<4;q++) d[i][j][q]=0.f;

    int nkc = K >> 6;

    uint32_t aoff = (uint32_t)((wm*32 + (lane & 15))*PITCH + ((lane >> 4) & 1)*16);
    uint32_t boff = (uint32_t)((wn*64 + (lane & 7) + ((lane >> 4) & 1)*8)*PITCH + ((lane >> 3) & 1)*16);

    auto do_mma = [&](int st){
        uint32_t base = smBase + (uint32_t)st*STG3;
        #pragma unroll
        for (int ks=0; ks<4; ks++){
            uint32_t a_[2][4], b_[4][4];
            uint32_t aT = base + aoff + ks*32;
            uint32_t bT = base + ATS + boff + ks*32;
            #pragma unroll
            for (int mi=0; mi<2; mi++) ldsm4(a_[mi], aT + mi*16*PITCH);
            #pragma unroll
            for (int np_=0; np_<4; np_++) ldsm4(b_[np_], bT + np_*16*PITCH);
            #pragma unroll
            for (int mi=0; mi<2; mi++)
                #pragma unroll
                for (int nj=0; nj<8; nj++)
                    mma16816(d[mi][nj], a_[mi], b_[nj>>1][(nj&1)*2], b_[nj>>1][(nj&1)*2+1]);
        }
    };

    if (A32 == nullptr){
        // ---- fp16 A path: 6 x 16B per thread (ah 1024 | wh 2048) ----
        const __half* AhR = Ah + (size_t)by*128*lda;
        auto load_chunk = [&](int kc, int st){
            uint32_t base = smBase + (uint32_t)st*STG3;
            #pragma unroll
            for (int t=0;t<6;t++){
                int it = tid + t*512;
                const __half* src; uint32_t dst;
                if (it < 1024){
                    int row = it >> 3, seg = it & 7;
                    src = AhR + (size_t)row*lda + kc*64 + seg*8;
                    dst = base + row*PITCH + seg*16;
                } else {
                    int j = it - 1024;
                    int row = j >> 3, seg = j & 7;
                    src = WhS + (size_t)row*K + kc*64 + seg*8;
                    dst = base + ATS + row*PITCH + seg*16;
                }
                cp16(dst, src);
            }
            cp_commit();
        };
        load_chunk(0, 0);
        if (nkc > 1) load_chunk(1, 1);
        for (int c=0; c<nkc; c++){
            int st = c % 3;
            if (c+2 < nkc) load_chunk(c+2, (c+2)%3);
            if (c+2 < nkc) cp_wait<2>();
            else if (c+1 < nkc) cp_wait<1>();
            else cp_wait<0>();
            __syncthreads();
            do_mma(st);
            __syncthreads();
        }
    } else {
        // ---- fp32 A path (pass-0): LDG.128 + fp16 convert ----
        const float* aptr[4];
        bool avalid[4];
        int aRow[4], aSeg[4];
        #pragma unroll
        for (int t=0;t<4;t++){
            int j = tid + t*512;          // 2048 items: 128 rows x 16 float4-segs
            aRow[t] = j >> 4; aSeg[t] = j & 15;
            int src = g_n2o[by*128 + aRow[t]];
            avalid[t] = (src >= 0);
            aptr[t] = A32 + (size_t)(src < 0 ? 0 : src)*AEV;
        }
        auto loadW = [&](int kc, int st){
            uint32_t base = smBase + (uint32_t)st*STG3 + ATS;
            #pragma unroll
            for (int t=0;t<4;t++){
                int j = tid + t*512;      // 2048 items: 256 rows x 8 segs(16B)
                int row = j >> 3, seg = j & 7;
                const __half* src = WhS + (size_t)row*K + kc*64 + seg*8;
                cp16(base + row*PITCH + seg*16, src);
            }
            cp_commit();
        };
        float4 R[4];
        auto ldgA = [&](int kc){
            #pragma unroll
            for (int t=0;t<4;t++){
                int col = kc*64 + aSeg[t]*4;
                if (avalid[t] && col < AEV) R[t] = *(const float4*)(aptr[t] + col);
                else R[t] = make_float4(0.f,0.f,0.f,0.f);
            }
        };
        auto stsA = [&](int st){
            uint32_t base = (uint32_t)st*STG3;
            #pragma unroll
            for (int t=0;t<4;t++){
                __half h[4];
                h[0] = __float2half_rn(R[t].x);
                h[1] = __float2half_rn(R[t].y);
                h[2] = __float2half_rn(R[t].z);
                h[3] = __float2half_rn(R[t].w);
                uint32_t off = base + (uint32_t)(aRow[t]*PITCH + aSeg[t]*8);
                *(uint64_t*)(sm + off) = *(const uint64_t*)h;
            }
        };
        loadW(0, 0);
        if (nkc > 1) loadW(1, 1);
        ldgA(0); stsA(0);
        if (nkc > 1) ldgA(1);
        for (int c=0; c<nkc; c++){
            int st = c % 3;
            if (c+2 < nkc) loadW(c+2, (c+2)%3);
            if (c+1 < nkc) stsA((c+1)%3);
            if (c+2 < nkc) ldgA(c+2);
            if (c+2 < nkc) cp_wait<2>();
            else if (c+1 < nkc) cp_wait<1>();
            else cp_wait<0>();
            __syncthreads();
            do_mma(st);
            __syncthreads();
        }
    }

    const float* bp = bias + sp*Nout + wn*64;
    int rowLo = wm*32 + (lane >> 2);
    int colCta = wn*64;
    #pragma unroll
    for (int mi=0; mi<2; mi++){
        #pragma unroll
        for (int nj=0; nj<8; nj++){
            int c0 = nj*8 + 2*(lane & 3);
            float b0 = bp[c0], b1 = bp[c0+1];
            #pragma unroll
            for (int h=0; h<2; h++){
                size_t gr = (size_t)by*128 + rowLo + mi*16 + h*8;
                float x0 = gelu_tanh(d[mi][nj][2*h]   + b0);
                float x1 = gelu_tanh(d[mi][nj][2*h+1] + b1);
                int col = colCta + c0;
                if (C32){
                    *(float2*)(C32 + gr*ldc32 + col) = make_float2(x0, x1);
                }
                if (Ch){
                    uint32_t hh = (uint32_t)__half_as_ushort(__float2half_rn(x0)) |
                                  ((uint32_t)__half_as_ushort(__float2half_rn(x1)) << 16);
                    *(uint32_t*)(Ch + gr*ldcb + col) = hh;
                }
            }
        }
    }
}

// ---------------- CSR gather: merged[r][t] = sum_nb neigh[nb][t]*w ----------
__global__ void __launch_bounds__(128) mpgather_kernel(int mode){
    int r = blockIdx.x, t = threadIdx.x;
    int s = g_roff[r], e = g_roff[r+1];
    float acc = 0.f;
    int j = s;
    for (; j+3 < e; j += 4){
        int   n0 = g_nbr[j],   n1 = g_nbr[j+1], n2 = g_nbr[j+2], n3 = g_nbr[j+3];
        float w0 = g_w[j],     w1 = g_w[j+1],   w2 = g_w[j+2],   w3 = g_w[j+3];
        float x0 = g_neigh[(size_t)n0*NOUT + t];
        float x1 = g_neigh[(size_t)n1*NOUT + t];
        float x2 = g_neigh[(size_t)n2*NOUT + t];
        float x3 = g_neigh[(size_t)n3*NOUT + t];
        acc = fmaf(x0, w0, acc);
        acc = fmaf(x1, w1, acc);
        acc = fmaf(x2, w2, acc);
        acc = fmaf(x3, w3, acc);
    }
    for (; j < e; j++)
        acc = fmaf(g_neigh[(size_t)g_nbr[j]*NOUT + t], g_w[j], acc);
    if (mode == 0){
        g_f1h[(size_t)r*FIN + 256 + t] = __float2half_rn(acc);
    } else {
        g_feat2[(size_t)r*FIN + 256 + t] = acc;
    }
}

// ---------------- final routed linear (FIN->1) + outputs --------------------
__global__ void __launch_bounds__(256) final_kernel(const int* __restrict__ species,
                                                    const float* __restrict__ Wf,
                                                    const float* __restrict__ bf,
                                                    float* __restrict__ out){
    int gt = blockIdx.x*256 + threadIdx.x;
    int i = gt >> 5, lane = gt & 31;
    if (i >= NATOMS) return;
    int s = species[i];
    int r = g_p2n[i];
    const float* f = g_feat2 + (size_t)r*FIN;
    const float* w = Wf + s*FIN;
    float sum = 0.f;
    #pragma unroll
    for (int j=0;j<12;j++){
        int k = lane + 32*j;
        sum = fmaf(f[k], w[k], sum);
    }
    #pragma unroll
    for (int o=16;o;o>>=1) sum += __shfl_xor_sync(0xffffffffu, sum, o);
    if (lane == 0){
        float pre = sum + bf[s];
        g_pre[i] = pre;
        out[2*NATOMS + i] = pre;
        out[i] = (float)s;
    }
}

// ---------------- per-molecule charge redistribution -------------------------
__global__ void charge_kernel(const float* __restrict__ tq, float* __restrict__ out){
    __shared__ float ss[4];
    int b = blockIdx.x, a = threadIdx.x;
    float p = g_pre[b*NA + a];
    float v = p;
    #pragma unroll
    for (int o=16;o;o>>=1) v += __shfl_xor_sync(0xffffffffu, v, o);
    int w = a>>5, lane = a&31;
    if (lane == 0) ss[w] = v;
    __syncthreads();
    float sum = ss[0]+ss[1]+ss[2]+ss[3];
    out[NATOMS + b*NA + a] = p + (tq[b] - sum)*(1.0f/128.0f);
}

// ---------------- launch -----------------------------------------------------
extern "C" void kernel_launch(void* const* d_in, const int* in_sizes, int n_in,
                              void* d_out, int out_size){
    const int*   species = (const int*)  d_in[0];
    const float* aev     = (const float*)d_in[1];
    const int*   ai12    = (const int*)  d_in[2];
    const float* dist    = (const float*)d_in[3];
    const float* tq      = (const float*)d_in[4];
    const float* Wm0     = (const float*)d_in[5];
    const float* bm0     = (const float*)d_in[6];
    const float* Wn0     = (const float*)d_in[7];
    const float* bn0     = (const float*)d_in[8];
    const float* Wm1     = (const float*)d_in[9];
    const float* bm1     = (const float*)d_in[10];
    const float* Wn1     = (const float*)d_in[11];
    const float* bn1     = (const float*)d_in[12];
    const float* Wf      = (const float*)d_in[13];
    const float* bf      = (const float*)d_in[14];
    const float* factor  = (const float*)d_in[15];
    const float* prefac  = (const float*)d_in[16];
    float* out = (float*)d_out;

    __half *f1h, *f2h, *wm0h, *wn0h, *wm1h, *wn1h;
    float *feat2, *neigh;
    cudaGetSymbolAddress((void**)&f1h,  g_f1h);
    cudaGetSymbolAddress((void**)&f2h,  g_f2h);
    cudaGetSymbolAddress((void**)&wm0h, g_wm0h);
    cudaGetSymbolAddress((void**)&wn0h, g_wn0h);
    cudaGetSymbolAddress((void**)&wm1h, g_wm1h);
    cudaGetSymbolAddress((void**)&wn1h, g_wn1h);
    cudaGetSymbolAddress((void**)&feat2, g_feat2);
    cudaGetSymbolAddress((void**)&neigh, g_neigh);

    cudaFuncSetAttribute(tgemm128_kernel, cudaFuncAttributeMaxDynamicSharedMemorySize, 2*STG128);
    cudaFuncSetAttribute(tgemm256_kernel, cudaFuncAttributeMaxDynamicSharedMemorySize, 3*STG3);

    // side streams + events (created once; never destroyed -> capture-safe)
    static cudaStream_t s1 = 0, s2 = 0;
    static cudaEvent_t evStart=0, evPerm=0, evW0m=0, evWn0=0, evW1m=0, evWrest=0, evCsr=0;
    if (!s1){
        cudaStreamCreateWithFlags(&s1, cudaStreamNonBlocking);
        cudaStreamCreateWithFlags(&s2, cudaStreamNonBlocking);
        cudaEventCreateWithFlags(&evStart, cudaEventDisableTiming);
        cudaEventCreateWithFlags(&evPerm,  cudaEventDisableTiming);
        cudaEventCreateWithFlags(&evW0m,   cudaEventDisableTiming);
        cudaEventCreateWithFlags(&evWn0,   cudaEventDisableTiming);
        cudaEventCreateWithFlags(&evW1m,   cudaEventDisableTiming);
        cudaEventCreateWithFlags(&evWrest, cudaEventDisableTiming);
        cudaEventCreateWithFlags(&evCsr,   cudaEventDisableTiming);
    }

    // fork s2: weight prep in consumption order
    cudaEventRecord(evStart, 0);
    cudaStreamWaitEvent(s2, evStart, 0);
    wprep_kernel<<<(NSP*MO*AEVP)/256, 256, 0, s2>>>(Wm0, wm0h, AEV, MO, AEVP);
    cudaEventRecord(evW0m, s2);
    wprep_kernel<<<(NSP*NOUT*MO)/256, 256, 0, s2>>>(Wn0, wn0h, MO, NOUT, MO);
    cudaEventRecord(evWn0, s2);
    wprep_kernel<<<(NSP*MO*FIN)/256, 256, 0, s2>>>(Wm1, wm1h, FIN, MO, FIN);
    cudaEventRecord(evW1m, s2);
    wprep_kernel<<<(NSP*NOUT*MO)/256, 256, 0, s2>>>(Wn1, wn1h, MO, NOUT, MO);
    cudaEventRecord(evWrest, s2);

    // main: permutation; fork s1: CSR build
    perm_kernel<<<1, 1024>>>(species);
    cudaEventRecord(evPerm, 0);
    cudaStreamWaitEvent(s1, evPerm, 0);
    edge_kernel<<<NP/256, 256, 0, s1>>>(ai12, dist, factor, prefac);
    scan_kernel<<<1, 1024, 0, s1>>>();
    fill_kernel<<<NP/256, 256, 0, s1>>>();
    cudaEventRecord(evCsr, s1);

    // pass 0
    cudaStreamWaitEvent(0, evW0m, 0);
    tgemm256_kernel<<<NT, 512, 3*STG3>>>(aev,
        (__half*)0, 0, wm0h, bm0,
        AEVP, (float*)0, 0, f1h, FIN);
    cudaStreamWaitEvent(0, evWn0, 0);
    tgemm128_kernel<<<NT, 256, 2*STG128>>>(f1h, FIN, wn0h, bn0,
        MO, neigh, NOUT, 1);
    cudaStreamWaitEvent(0, evCsr, 0);
    mpgather_kernel<<<NPAD, 128>>>(0);

    // pass 1
    cudaStreamWaitEvent(0, evW1m, 0);
    tgemm256_kernel<<<NT, 512, 3*STG3>>>((const float*)0,
        f1h, FIN, wm1h, bm1,
        FIN, feat2, FIN, f2h, MO);
    cudaStreamWaitEvent(0, evWrest, 0);
    tgemm128_kernel<<<NT, 256, 2*STG128>>>(f2h, MO, wn1h, bn1,
        MO, neigh, NOUT, 1);
    mpgather_kernel<<<NPAD, 128>>>(1);

    // outputs
    final_kernel <<<NATOMS*32/256, 256>>>(species, Wf, bf, out);
    charge_kernel<<<NB, NA>>>(tq, out);
}